// round 16
// baseline (speedup 1.0000x reference)
#include <cuda_runtime.h>
#include <cuda_bf16.h>
#include <cstdint>

#define LSEQ 2048
#define NBH  16
#define NT   1024
#define SCALE 0.07216878364870323f   // 1/sqrt(3*64)
#define SSTR 2052
#define KSTR 68
#define VSTR2 132

#define OFF_KV 131328                // sS = 16*2052*4
#define KBUF   34816                 // 128*68*4
#define VBUF   33792                 // 64*132*4
#define OFF_B0 200960                // 2 x 8192
#define OFF_M0 217344                // 2 x 2048
#define OFF_Q  221440                // 4352
#define SMEM_BYTES 225792

__device__ uint32_t g_qp[(size_t)NBH * LSEQ * 64];
__device__ uint32_t g_kp[(size_t)NBH * LSEQ * 64];
__device__ uint32_t g_vp[(size_t)NBH * 64 * LSEQ];         // [bh][dim][j]
__device__ float    g_bias[(size_t)NBH * LSEQ * LSEQ];     // TS+LS
__device__ unsigned char g_m8[(size_t)2 * LSEQ * LSEQ];    // mask 0/1 bytes

__device__ __forceinline__ uint32_t packsplit(float x) {
    __nv_bfloat16 h = __float2bfloat16(x);
    float hf = __bfloat162float(h);
    __nv_bfloat16 l = __float2bfloat16(x - hf);
    unsigned short hs = *(unsigned short*)&h, ls = *(unsigned short*)&l;
    return (uint32_t)hs | ((uint32_t)ls << 16);
}
__device__ __forceinline__ uint32_t smem_u32(const void* p) {
    uint32_t a;
    asm("{ .reg .u64 t; cvta.to.shared.u64 t, %1; cvt.u32.u64 %0, t; }" : "=r"(a) : "l"(p));
    return a;
}
#define PHI(w0,w1) __byte_perm((w0), (w1), 0x5410)
#define PLO(w0,w1) __byte_perm((w0), (w1), 0x7632)
#define MMA(c, a0,a1,a2,a3, b0,b1) \
  asm volatile("mma.sync.aligned.m16n8k16.row.col.f32.bf16.bf16.f32 " \
    "{%0,%1,%2,%3}, {%4,%5,%6,%7}, {%8,%9}, {%0,%1,%2,%3};" \
    : "+f"((c)[0]), "+f"((c)[1]), "+f"((c)[2]), "+f"((c)[3]) \
    : "r"(a0), "r"(a1), "r"(a2), "r"(a3), "r"(b0), "r"(b1))
#define CPA(dst, src)  asm volatile("cp.async.cg.shared.global [%0], [%1], 16;" :: "r"(dst), "l"(src))
#define CPA4(dst, src) asm volatile("cp.async.ca.shared.global [%0], [%1], 4;"  :: "r"(dst), "l"(src))
#define CPCOMMIT()     asm volatile("cp.async.commit_group;" ::: "memory")
#define CPWAIT0()      asm volatile("cp.async.wait_group 0;" ::: "memory")
#define CPWAIT1()      asm volatile("cp.async.wait_group 1;" ::: "memory")

// ---------------- prep: pack Q/K; transpose+pack V; bias add; mask bytes ----
__global__ void prep_kernel(const float* __restrict__ Q, const float* __restrict__ K,
                            const float* __restrict__ V, const unsigned char* __restrict__ M,
                            const float* __restrict__ TS, const float* __restrict__ LS)
{
    const int t = threadIdx.x;
    const int bid = blockIdx.x;
    if (bid < 1024) {
        #pragma unroll
        for (int i = 0; i < 2; i++) {
            size_t idx4 = (size_t)bid * 512 + t + (size_t)i * 256;
            float4 q = ((const float4*)Q)[idx4];
            ((uint4*)g_qp)[idx4] = make_uint4(packsplit(q.x), packsplit(q.y),
                                             packsplit(q.z), packsplit(q.w));
            float4 k = ((const float4*)K)[idx4];
            ((uint4*)g_kp)[idx4] = make_uint4(packsplit(k.x), packsplit(k.y),
                                             packsplit(k.z), packsplit(k.w));
        }
    } else if (bid < 1536) {
        __shared__ float sT[64 * 65];
        int bi = bid - 1024, bh = bi >> 5, jt = bi & 31;
        const float* Vb = V + ((size_t)bh * LSEQ + jt * 64) * 64;
        #pragma unroll
        for (int i = 0; i < 4; i++) {
            int q = t + i * 256, j = q >> 4, n4 = (q & 15) * 4;
            float4 v = *(const float4*)(Vb + (size_t)j * 64 + n4);
            sT[(n4+0)*65 + j] = v.x; sT[(n4+1)*65 + j] = v.y;
            sT[(n4+2)*65 + j] = v.z; sT[(n4+3)*65 + j] = v.w;
        }
        __syncthreads();
        #pragma unroll
        for (int i = 0; i < 4; i++) {
            int q = t + i * 256, dim = q >> 4, j4 = (q & 15) * 4;
            uint4 pw = make_uint4(packsplit(sT[dim*65 + j4]),
                                  packsplit(sT[dim*65 + j4 + 1]),
                                  packsplit(sT[dim*65 + j4 + 2]),
                                  packsplit(sT[dim*65 + j4 + 3]));
            *(uint4*)(g_vp + ((size_t)bh * 64 + dim) * LSEQ + jt * 64 + j4) = pw;
        }
    } else if (bid < 5632) {
        size_t base4 = (size_t)(bid - 1536) * 4096;
        #pragma unroll
        for (int i = 0; i < 16; i++) {
            size_t idx4 = base4 + t + (size_t)i * 256;
            float4 a = ((const float4*)TS)[idx4];
            float4 b = ((const float4*)LS)[idx4];
            a.x += b.x; a.y += b.y; a.z += b.z; a.w += b.w;
            ((float4*)g_bias)[idx4] = a;
        }
    } else {
        __shared__ int sF;
        if (t == 0) {
            const int* mi = (const int*)M; const float* mf = (const float*)M;
            bool okI = true, okF = true;
            for (int i = 0; i < 64; i++) {
                int vi = mi[i]; float vf = mf[i];
                if (vi != 0 && vi != 1)     okI = false;
                if (vf != 0.f && vf != 1.f) okF = false;
            }
            sF = okI ? 1 : (okF ? 2 : 0);
        }
        __syncthreads();
        const int flag = sF;
        size_t base = (size_t)(bid - 5632) * 8192;
        #pragma unroll
        for (int i = 0; i < 8; i++) {
            size_t e = base + ((size_t)t + i * 256) * 4;
            uchar4 o;
            if (flag == 1) { int4 v = *(const int4*)((const int*)M + e);
                o = make_uchar4(v.x?1:0, v.y?1:0, v.z?1:0, v.w?1:0); }
            else if (flag == 0) { uchar4 v = *(const uchar4*)(M + e);
                o = make_uchar4(v.x?1:0, v.y?1:0, v.z?1:0, v.w?1:0); }
            else { float4 v = *(const float4*)((const float*)M + e);
                o = make_uchar4(v.x!=0.f, v.y!=0.f, v.z!=0.f, v.w!=0.f); }
            *(uchar4*)(g_m8 + e) = o;
        }
    }
}

// ---------------- main fused kernel: warp-specialized phase 1 ----------------
__global__ __launch_bounds__(NT, 1)
void raa_kernel(float* __restrict__ O, float* __restrict__ P)
{
    extern __shared__ char smem[];
    float*    sS  = (float*)smem;
    uint32_t* sSw = (uint32_t*)smem;
    uint32_t* sQ  = (uint32_t*)(smem + OFF_Q);
    __shared__ float sRow[16];

    const int t = threadIdx.x, w = t >> 5, lane = t & 31;
    const int g = lane >> 2, tig = lane & 3;
    const int bh = blockIdx.y, i0 = blockIdx.x * 16;
    const uint32_t sb = smem_u32(smem);
    const uint32_t kbuf0 = sb + OFF_KV;

    if (t < 256) {
        int row = t >> 4, k4 = (t & 15) * 4;
        uint4 pw = *((const uint4*)(g_qp + ((size_t)bh * LSEQ + i0) * 64) + t);
        *(uint4*)(sQ + row * KSTR + k4) = pw;
    }

    const size_t growb = (size_t)bh * LSEQ + i0;
    const size_t mrowb = (size_t)(bh >> 3) * LSEQ + i0;
    const uint4* Kp = (const uint4*)(g_kp + (size_t)bh * LSEQ * 64);
    const int ew = w - 16;
    float rsum = 0.f;

    // prologue staging
    if (w < 16) {
        #pragma unroll
        for (int i = 0; i < 4; i++) {
            int idx = t + i * 512, j = idx >> 4, k4 = idx & 15;
            CPA(kbuf0 + (uint32_t)((j * KSTR + k4 * 4) * 4), (const void*)(Kp + j * 16 + k4));
        }
        CPCOMMIT();
    } else {
        CPA(sb + OFF_B0 + (uint32_t)(ew * 512 + lane * 16),
            (const void*)(g_bias + (growb + ew) * LSEQ + lane * 4));
        CPA4(sb + OFF_M0 + (uint32_t)(ew * 128 + lane * 4),
             (const void*)(g_m8 + (mrowb + ew) * LSEQ + lane * 4));
        CPCOMMIT();
    }
    __syncthreads();   // sQ ready

    for (int c = 0; c < 16; c++) {
        if (w < 16) { CPWAIT0(); } else { CPWAIT1(); }
        __syncthreads();
        if (w < 16) {
            if (c + 1 < 16) {
                uint32_t kdst = kbuf0 + ((c + 1) & 1) * KBUF;
                const uint4* src = Kp + (size_t)(c + 1) * 2048;
                #pragma unroll
                for (int i = 0; i < 4; i++) {
                    int idx = t + i * 512, j = idx >> 4, k4 = idx & 15;
                    CPA(kdst + (uint32_t)((j * KSTR + k4 * 4) * 4), (const void*)(src + j * 16 + k4));
                }
                CPCOMMIT();
            }
            const uint32_t* sK = (const uint32_t*)(smem + OFF_KV + (c & 1) * KBUF);
            float acc[4] = {0.f, 0.f, 0.f, 0.f};
            const int jrow = w * 8 + g;
            #pragma unroll
            for (int ks = 0; ks < 4; ks++) {
                int c0 = ks * 16 + 2 * tig;
                uint2 a0 = *(const uint2*)(sQ + g * KSTR + c0);
                uint2 a1 = *(const uint2*)(sQ + (g + 8) * KSTR + c0);
                uint2 a2 = *(const uint2*)(sQ + g * KSTR + c0 + 8);
                uint2 a3 = *(const uint2*)(sQ + (g + 8) * KSTR + c0 + 8);
                uint32_t qh0 = PHI(a0.x, a0.y), ql0 = PLO(a0.x, a0.y);
                uint32_t qh1 = PHI(a1.x, a1.y), ql1 = PLO(a1.x, a1.y);
                uint32_t qh2 = PHI(a2.x, a2.y), ql2 = PLO(a2.x, a2.y);
                uint32_t qh3 = PHI(a3.x, a3.y), ql3 = PLO(a3.x, a3.y);
                uint2 b01 = *(const uint2*)(sK + jrow * KSTR + c0);
                uint2 b23 = *(const uint2*)(sK + jrow * KSTR + c0 + 8);
                uint32_t b0 = PHI(b01.x, b01.y), l0 = PLO(b01.x, b01.y);
                uint32_t b1 = PHI(b23.x, b23.y), l1 = PLO(b23.x, b23.y);
                MMA(acc, qh0, qh1, qh2, qh3, b0, b1);
                MMA(acc, qh0, qh1, qh2, qh3, l0, l1);
                MMA(acc, ql0, ql1, ql2, ql3, b0, b1);
            }
            const int col = c * 128 + w * 8 + 2 * tig;
            *(float2*)(sS + (size_t)g * SSTR + col)       = make_float2(acc[0], acc[1]);
            *(float2*)(sS + (size_t)(g + 8) * SSTR + col) = make_float2(acc[2], acc[3]);
        } else {
            if (c >= 1) {
                const int cc = c - 1;
                const float* bsm = (const float*)(smem + OFF_B0 + (cc & 1) * 8192);
                const unsigned char* msm = (const unsigned char*)(smem + OFF_M0 + (cc & 1) * 2048);
                float* sSr = sS + (size_t)ew * SSTR + cc * 128 + lane * 4;
                float4 sv = *(const float4*)sSr;
                float4 b4 = *(const float4*)(bsm + ew * 128 + lane * 4);
                uchar4 m4 = *(const uchar4*)(msm + ew * 128 + lane * 4);
                float e0 = m4.x ? 0.f : __expf((sv.x + b4.x) * SCALE);
                float e1 = m4.y ? 0.f : __expf((sv.y + b4.y) * SCALE);
                float e2 = m4.z ? 0.f : __expf((sv.z + b4.z) * SCALE);
                float e3 = m4.w ? 0.f : __expf((sv.w + b4.w) * SCALE);
                *(float4*)sSr = make_float4(e0, e1, e2, e3);
                rsum += (e0 + e1) + (e2 + e3);
            }
            if (c + 1 < 16) {
                CPA(sb + OFF_B0 + ((c + 1) & 1) * 8192 + (uint32_t)(ew * 512 + lane * 16),
                    (const void*)(g_bias + (growb + ew) * LSEQ + (c + 1) * 128 + lane * 4));
                CPA4(sb + OFF_M0 + ((c + 1) & 1) * 2048 + (uint32_t)(ew * 128 + lane * 4),
                     (const void*)(g_m8 + (mrowb + ew) * LSEQ + (c + 1) * 128 + lane * 4));
                CPCOMMIT();
            }
        }
    }
    if (w >= 16) { CPWAIT0(); }
    __syncthreads();   // MMA chunk-15 stores visible
    if (w >= 16) {
        const int cc = 15;
        const float* bsm = (const float*)(smem + OFF_B0 + (cc & 1) * 8192);
        const unsigned char* msm = (const unsigned char*)(smem + OFF_M0 + (cc & 1) * 2048);
        float* sSr = sS + (size_t)ew * SSTR + cc * 128 + lane * 4;
        float4 sv = *(const float4*)sSr;
        float4 b4 = *(const float4*)(bsm + ew * 128 + lane * 4);
        uchar4 m4 = *(const uchar4*)(msm + ew * 128 + lane * 4);
        float e0 = m4.x ? 0.f : __expf((sv.x + b4.x) * SCALE);
        float e1 = m4.y ? 0.f : __expf((sv.y + b4.y) * SCALE);
        float e2 = m4.z ? 0.f : __expf((sv.z + b4.z) * SCALE);
        float e3 = m4.w ? 0.f : __expf((sv.w + b4.w) * SCALE);
        *(float4*)sSr = make_float4(e0, e1, e2, e3);
        rsum += (e0 + e1) + (e2 + e3);
        #pragma unroll
        for (int k = 16; k >= 1; k >>= 1)
            rsum += __shfl_xor_sync(0xffffffffu, rsum, k);
        if (lane == 0) sRow[ew] = 1.0f / rsum;
    }
    // issue V chunk-0 copy (hides behind phase 3)
    const uint4* Vp = (const uint4*)(g_vp + (size_t)bh * 64 * LSEQ);
    {
        #pragma unroll
        for (int i = 0; i < 2; i++) {
            int idx = t + i * NT, dim = idx >> 5, u4 = idx & 31;
            CPA(kbuf0 + (uint32_t)((dim * VSTR2 + u4 * 4) * 4),
                (const void*)(Vp + (size_t)dim * 512 + u4));
        }
        CPCOMMIT();
    }
    __syncthreads();

    // ---- Phase 3: normalize, write P, repack packed bf16 in place ----
    {
        float* Pb = P + ((size_t)bh * LSEQ + i0) * LSEQ;
        #pragma unroll
        for (int it = 0; it < 8; it++) {
            int task = t + it * NT;
            int r = task >> 9, c4 = task & 511;
            float rinv = sRow[r];
            float4 e = ((const float4*)(sS + (size_t)r * SSTR))[c4];
            e.x *= rinv; e.y *= rinv; e.z *= rinv; e.w *= rinv;
            *(float4*)(Pb + (size_t)r * LSEQ + c4 * 4) = e;
            uint4 pw = make_uint4(packsplit(e.x), packsplit(e.y), packsplit(e.z), packsplit(e.w));
            ((uint4*)(sSw + (size_t)r * SSTR))[c4] = pw;
        }
    }

    // ---- Phase 4: O = P V; warp = (j-window, dim-quarter) ----
    const int x = w & 7, q4 = w >> 3;
    float oc[2][4];
    #pragma unroll
    for (int nt = 0; nt < 2; nt++)
        oc[nt][0] = oc[nt][1] = oc[nt][2] = oc[nt][3] = 0.f;
    for (int c = 0; c < 16; c++) {
        CPWAIT0();
        __syncthreads();
        if (c + 1 < 16) {
            uint32_t db = kbuf0 + ((c + 1) & 1) * VBUF;
            #pragma unroll
            for (int i = 0; i < 2; i++) {
                int idx = t + i * NT, dim = idx >> 5, u4 = idx & 31;
                CPA(db + (uint32_t)((dim * VSTR2 + u4 * 4) * 4),
                    (const void*)(Vp + (size_t)dim * 512 + (c + 1) * 32 + u4));
            }
            CPCOMMIT();
        }
        const uint32_t* sV = (const uint32_t*)(smem + OFF_KV + (c & 1) * VBUF);
        int ac = c * 128 + x * 16 + 2 * tig;
        uint2 a0 = *(const uint2*)(sSw + (size_t)g * SSTR + ac);
        uint2 a1 = *(const uint2*)(sSw + (size_t)(g + 8) * SSTR + ac);
        uint2 a2 = *(const uint2*)(sSw + (size_t)g * SSTR + ac + 8);
        uint2 a3 = *(const uint2*)(sSw + (size_t)(g + 8) * SSTR + ac + 8);
        uint32_t ah0 = PHI(a0.x, a0.y), ah1 = PHI(a1.x, a1.y);
        uint32_t ah2 = PHI(a2.x, a2.y), ah3 = PHI(a3.x, a3.y);
        uint32_t al0 = PLO(a0.x, a0.y), al1 = PLO(a1.x, a1.y);
        uint32_t al2 = PLO(a2.x, a2.y), al3 = PLO(a3.x, a3.y);
        int jb2 = x * 16 + 2 * tig;
        #pragma unroll
        for (int nt = 0; nt < 2; nt++) {
            int dim = q4 * 16 + 8 * nt + g;
            uint2 b01 = *(const uint2*)(sV + dim * VSTR2 + jb2);
            uint2 b23 = *(const uint2*)(sV + dim * VSTR2 + jb2 + 8);
            uint32_t bh0 = PHI(b01.x, b01.y), bl0 = PLO(b01.x, b01.y);
            uint32_t bh1 = PHI(b23.x, b23.y), bl1 = PLO(b23.x, b23.y);
            MMA(oc[nt], ah0, ah1, ah2, ah3, bh0, bh1);
            MMA(oc[nt], ah0, ah1, ah2, ah3, bl0, bl1);
            MMA(oc[nt], al0, al1, al2, al3, bh0, bh1);
        }
    }
    __syncthreads();
    {
        float* part = (float*)(smem + OFF_KV);
        #pragma unroll
        for (int nt = 0; nt < 2; nt++) {
            int dimb = q4 * 16 + 8 * nt + 2 * tig;
            *(float2*)(part + x * 1024 + g * 64 + dimb)       = make_float2(oc[nt][0], oc[nt][1]);
            *(float2*)(part + x * 1024 + (g + 8) * 64 + dimb) = make_float2(oc[nt][2], oc[nt][3]);
        }
    }
    __syncthreads();
    {
        const float* part = (const float*)(smem + OFF_KV);
        int row = t >> 6, dim = t & 63;
        float s = 0.f;
        #pragma unroll
        for (int xx = 0; xx < 8; xx++) s += part[xx * 1024 + row * 64 + dim];
        O[((size_t)bh * LSEQ + i0 + row) * 64 + dim] = s;
    }
}

extern "C" void kernel_launch(void* const* d_in, const int* in_sizes, int n_in,
                              void* d_out, int out_size)
{
    const float* Q  = (const float*)d_in[0];
    const float* K  = (const float*)d_in[1];
    const float* V  = (const float*)d_in[2];
    const unsigned char* M = (const unsigned char*)d_in[3];
    const float* TS = (const float*)d_in[4];
    const float* LS = (const float*)d_in[5];
    float* out = (float*)d_out;
    float* O = out;
    float* P = out + (size_t)NBH * LSEQ * 64;

    prep_kernel<<<6656, 256>>>(Q, K, V, M, TS, LS);
    cudaFuncSetAttribute(raa_kernel, cudaFuncAttributeMaxDynamicSharedMemorySize, SMEM_BYTES);
    dim3 grid(LSEQ / 16, NBH);
    raa_kernel<<<grid, NT, SMEM_BYTES>>>(O, P);
}